// round 3
// baseline (speedup 1.0000x reference)
#include <cuda_runtime.h>
#include <math.h>

// Problem constants
#define B_ 2
#define S_ 2048
#define D_ 1024
#define H_ 16
#define DH_ 64
#define BS_ (B_ * S_)
#define INV_SQRT_DH 0.125f

// Scratch (device globals: no runtime allocation allowed)
__device__ float g_Q[BS_ * D_];      // q projection, [B*S, D] == [B, S, H, DH]
__device__ float g_attn[BS_ * D_];   // per-head attention output (pre out-proj)
__device__ float g_M[H_ * DH_ * DH_]; // folded per-head 64x64 matrices (incl. 1/sqrt(dh))

// ---------------------------------------------------------------------------
// Generic C = A @ W^T + bias (+ residual). A:[M,K] row-major, W:[N,K] row-major.
// 64x64 block tile, BK=16, 256 threads, 4x4 microtile.
// ---------------------------------------------------------------------------
template <bool RESID>
__global__ __launch_bounds__(256) void gemm_xwT(
    const float* __restrict__ A, const float* __restrict__ W,
    const float* __restrict__ bias, const float* __restrict__ R,
    float* __restrict__ C, int M, int N, int K)
{
    __shared__ float As[16][68];  // [k][m], pad 68 keeps f4 aligned + low store conflicts
    __shared__ float Ws[16][68];  // [k][n]
    const int tid = threadIdx.x;
    const int tx = tid & 15, ty = tid >> 4;
    const int m0 = blockIdx.y * 64, n0 = blockIdx.x * 64;

    float acc[4][4] = {};
    for (int k0 = 0; k0 < K; k0 += 16) {
#pragma unroll
        for (int e = 0; e < 4; e++) {
            int idx = tid + e * 256;
            int r = idx >> 4, kk = idx & 15;
            As[kk][r] = A[(size_t)(m0 + r) * K + k0 + kk];
            Ws[kk][r] = W[(size_t)(n0 + r) * K + k0 + kk];
        }
        __syncthreads();
#pragma unroll
        for (int kk = 0; kk < 16; kk++) {
            float4 a4 = *(const float4*)&As[kk][ty * 4];
            float4 b4 = *(const float4*)&Ws[kk][tx * 4];
            float av[4] = {a4.x, a4.y, a4.z, a4.w};
            float bv[4] = {b4.x, b4.y, b4.z, b4.w};
#pragma unroll
            for (int i = 0; i < 4; i++)
#pragma unroll
                for (int j = 0; j < 4; j++) acc[i][j] += av[i] * bv[j];
        }
        __syncthreads();
    }
#pragma unroll
    for (int i = 0; i < 4; i++) {
        int m = m0 + ty * 4 + i;
#pragma unroll
        for (int j = 0; j < 4; j++) {
            int n = n0 + tx * 4 + j;
            float v = acc[i][j] + bias[n];
            if (RESID) v += R[(size_t)m * N + n];
            C[(size_t)m * N + n] = v;
        }
    }
}

// ---------------------------------------------------------------------------
// Precompute M_h[d][f] = sum_e W_q[e, h*DH+d] * W_v[e, h*DH+f], scaled by 1/sqrt(dh).
// One block per head. 256 threads, 4x4 microtile over the 64x64 output.
// ---------------------------------------------------------------------------
__global__ __launch_bounds__(256) void compute_M_kernel(
    const float* __restrict__ Wq, const float* __restrict__ Wv)
{
    __shared__ float Aq[32][68];
    __shared__ float Av[32][68];
    const int h = blockIdx.x;
    const int tid = threadIdx.x;
    const int tx = tid & 15, ty = tid >> 4;

    float acc[4][4] = {};
    for (int e0 = 0; e0 < D_; e0 += 32) {
#pragma unroll
        for (int e = 0; e < 8; e++) {
            int idx = tid + e * 256;
            int ee = idx >> 6, c = idx & 63;
            Aq[ee][c] = Wq[(size_t)(e0 + ee) * D_ + h * DH_ + c];
            Av[ee][c] = Wv[(size_t)(e0 + ee) * D_ + h * DH_ + c];
        }
        __syncthreads();
#pragma unroll
        for (int ee = 0; ee < 32; ee++) {
            float4 a4 = *(const float4*)&Aq[ee][ty * 4];
            float4 b4 = *(const float4*)&Av[ee][tx * 4];
            float av[4] = {a4.x, a4.y, a4.z, a4.w};
            float bv[4] = {b4.x, b4.y, b4.z, b4.w};
#pragma unroll
            for (int i = 0; i < 4; i++)
#pragma unroll
                for (int j = 0; j < 4; j++) acc[i][j] += av[i] * bv[j];
        }
        __syncthreads();
    }
#pragma unroll
    for (int i = 0; i < 4; i++)
#pragma unroll
        for (int j = 0; j < 4; j++)
            g_M[h * DH_ * DH_ + (ty * 4 + i) * DH_ + tx * 4 + j] =
                acc[i][j] * INV_SQRT_DH;
}

// ---------------------------------------------------------------------------
// Flash-style L2 attention. One block = one (b,h) + a 64-query tile.
// Scores = 2/sqrt(dh) * q_s.q_t - ||q_t||^2/sqrt(dh)  (row constant cancelled),
// online softmax over key tiles, O = P @ Q(keys), epilogue O2 = (O/l) @ M_h.
// All smem rows padded to 65 floats: scalar accesses land at <=2-way conflicts.
// ---------------------------------------------------------------------------
__global__ __launch_bounds__(256) void attn_kernel(const int* __restrict__ mask)
{
    extern __shared__ float sm[];
    float* Qs = sm;               // [64][65] query tile [r][d]
    float* Ks = sm + 64 * 65;     // [64][65] key tile [t][d] (also V; also M_h at epilogue)
    float* Ps = sm + 2 * 64 * 65; // [64][65] P tile [r][t] (also normalized O at epilogue)
    float* kb = sm + 3 * 64 * 65; // [64] per-key bias (masked)

    const int tid = threadIdx.x;
    const int tx = tid & 15, ty = tid >> 4;
    const int qt = blockIdx.x;
    const int b = blockIdx.y >> 4;   // / H_
    const int h = blockIdx.y & 15;   // % H_
    const float* Qg = g_Q + (size_t)(b * S_) * D_ + h * DH_;

    // Load Q tile (64 rows x 64 d), float4 global reads, scalar smem stores.
#pragma unroll
    for (int e = 0; e < 4; e++) {
        int idx = tid + e * 256;
        int r = idx >> 4, c4 = idx & 15;
        float4 v = *(const float4*)&Qg[(size_t)(qt * 64 + r) * D_ + c4 * 4];
        Qs[r * 65 + c4 * 4 + 0] = v.x;
        Qs[r * 65 + c4 * 4 + 1] = v.y;
        Qs[r * 65 + c4 * 4 + 2] = v.z;
        Qs[r * 65 + c4 * 4 + 3] = v.w;
    }

    float Oacc[4][4] = {};
    float mrow[4], lrow[4];
#pragma unroll
    for (int i = 0; i < 4; i++) { mrow[i] = -1e30f; lrow[i] = 0.0f; }

    for (int kt = 0; kt < S_ / 64; kt++) {
        __syncthreads();  // prev PV done (and Q tile visible on iter 0)
        // Load key tile
#pragma unroll
        for (int e = 0; e < 4; e++) {
            int idx = tid + e * 256;
            int r = idx >> 4, c4 = idx & 15;
            float4 v = *(const float4*)&Qg[(size_t)(kt * 64 + r) * D_ + c4 * 4];
            Ks[r * 65 + c4 * 4 + 0] = v.x;
            Ks[r * 65 + c4 * 4 + 1] = v.y;
            Ks[r * 65 + c4 * 4 + 2] = v.z;
            Ks[r * 65 + c4 * 4 + 3] = v.w;
        }
        __syncthreads();
        // Per-key bias: -||q_t||^2/sqrt(dh), or -9e15 if masked
        if (tid < 64) {
            float s = 0.0f;
#pragma unroll
            for (int d = 0; d < 64; d++) { float q = Ks[tid * 65 + d]; s += q * q; }
            int mv = mask[b * S_ + kt * 64 + tid];
            kb[tid] = (mv == 0) ? -9e15f : (-s * INV_SQRT_DH);
        }
        __syncthreads();

        // S tile = Q @ K^T (4x4 microtile per thread)
        float sc[4][4] = {};
#pragma unroll
        for (int d = 0; d < 64; d++) {
            float av[4], bv[4];
#pragma unroll
            for (int i = 0; i < 4; i++) av[i] = Qs[(ty * 4 + i) * 65 + d];
#pragma unroll
            for (int j = 0; j < 4; j++) bv[j] = Ks[(tx * 4 + j) * 65 + d];
#pragma unroll
            for (int i = 0; i < 4; i++)
#pragma unroll
                for (int j = 0; j < 4; j++) sc[i][j] += av[i] * bv[j];
        }
        const float twoinv = 2.0f * INV_SQRT_DH;
#pragma unroll
        for (int i = 0; i < 4; i++)
#pragma unroll
            for (int j = 0; j < 4; j++)
                sc[i][j] = sc[i][j] * twoinv + kb[tx * 4 + j];

        // Online softmax (rows live in 16-lane groups along tx)
#pragma unroll
        for (int i = 0; i < 4; i++) {
            float mloc = fmaxf(fmaxf(sc[i][0], sc[i][1]), fmaxf(sc[i][2], sc[i][3]));
#pragma unroll
            for (int off = 8; off > 0; off >>= 1)
                mloc = fmaxf(mloc, __shfl_xor_sync(0xffffffffu, mloc, off, 16));
            float mnew = fmaxf(mrow[i], mloc);
            float alpha = __expf(mrow[i] - mnew);
            float psum = 0.0f;
#pragma unroll
            for (int j = 0; j < 4; j++) {
                float p = __expf(sc[i][j] - mnew);
                sc[i][j] = p;
                psum += p;
            }
#pragma unroll
            for (int off = 8; off > 0; off >>= 1)
                psum += __shfl_xor_sync(0xffffffffu, psum, off, 16);
            lrow[i] = lrow[i] * alpha + psum;
            mrow[i] = mnew;
#pragma unroll
            for (int j = 0; j < 4; j++) Oacc[i][j] *= alpha;
#pragma unroll
            for (int j = 0; j < 4; j++)
                Ps[(ty * 4 + i) * 65 + tx * 4 + j] = sc[i][j];
        }
        __syncthreads();

        // O += P @ K (values are the keys themselves)
#pragma unroll
        for (int t = 0; t < 64; t++) {
            float av[4], bv[4];
#pragma unroll
            for (int i = 0; i < 4; i++) av[i] = Ps[(ty * 4 + i) * 65 + t];
#pragma unroll
            for (int j = 0; j < 4; j++) bv[j] = Ks[t * 65 + tx * 4 + j];
#pragma unroll
            for (int i = 0; i < 4; i++)
#pragma unroll
                for (int j = 0; j < 4; j++) Oacc[i][j] += av[i] * bv[j];
        }
    }

    // Epilogue: normalize, then O2 = (O/l) @ M_h  (M already includes 1/sqrt(dh))
    __syncthreads();
#pragma unroll
    for (int i = 0; i < 4; i++) {
        float inv = 1.0f / lrow[i];
#pragma unroll
        for (int j = 0; j < 4; j++)
            Ps[(ty * 4 + i) * 65 + tx * 4 + j] = Oacc[i][j] * inv;
    }
#pragma unroll
    for (int e = 0; e < 16; e++) {
        int idx = tid + e * 256;
        int d = idx >> 6, f = idx & 63;
        Ks[d * 65 + f] = g_M[h * DH_ * DH_ + idx];
    }
    __syncthreads();

    float o2[4][4] = {};
#pragma unroll
    for (int d = 0; d < 64; d++) {
        float av[4], bv[4];
#pragma unroll
        for (int i = 0; i < 4; i++) av[i] = Ps[(ty * 4 + i) * 65 + d];
#pragma unroll
        for (int j = 0; j < 4; j++) bv[j] = Ks[d * 65 + tx * 4 + j];
#pragma unroll
        for (int i = 0; i < 4; i++)
#pragma unroll
            for (int j = 0; j < 4; j++) o2[i][j] += av[i] * bv[j];
    }
    float* Og = g_attn + (size_t)(b * S_) * D_ + h * DH_;
#pragma unroll
    for (int i = 0; i < 4; i++)
#pragma unroll
        for (int j = 0; j < 4; j++)
            Og[(size_t)(qt * 64 + ty * 4 + i) * D_ + tx * 4 + j] = o2[i][j];
}

// ---------------------------------------------------------------------------
// Launch: Q-proj GEMM -> M precompute -> attention -> out GEMM (+x residual)
// ---------------------------------------------------------------------------
extern "C" void kernel_launch(void* const* d_in, const int* in_sizes, int n_in,
                              void* d_out, int out_size)
{
    // metadata order: x, W_q, b_q, W_v, W_out, b_out, mask
    const float* x     = (const float*)d_in[0];
    const float* W_q   = (const float*)d_in[1];
    const float* b_q   = (const float*)d_in[2];
    const float* W_v   = (const float*)d_in[3];
    const float* W_out = (const float*)d_in[4];
    const float* b_out = (const float*)d_in[5];
    const int*   mask  = (const int*)d_in[6];
    float* out = (float*)d_out;

    float *pQ, *pA;
    cudaGetSymbolAddress((void**)&pQ, g_Q);
    cudaGetSymbolAddress((void**)&pA, g_attn);

    dim3 gge(D_ / 64, BS_ / 64);

    // 1) Q = x @ W_q^T + b_q
    gemm_xwT<false><<<gge, 256>>>(x, W_q, b_q, nullptr, pQ, BS_, D_, D_);

    // 2) per-head folded matrices M_h
    compute_M_kernel<<<H_, 256>>>(W_q, W_v);

    // 3) attention (flash-style) + per-head epilogue
    const int smemB = (3 * 64 * 65 + 64) * (int)sizeof(float);  // 50176 B
    cudaFuncSetAttribute(attn_kernel, cudaFuncAttributeMaxDynamicSharedMemorySize, smemB);
    attn_kernel<<<dim3(S_ / 64, B_ * H_), 256, smemB>>>(mask);

    // 4) out = x + attn @ W_out^T + b_out
    gemm_xwT<true><<<gge, 256>>>(pA, W_out, b_out, x, out, BS_, D_, D_);
}

// round 4
// speedup vs baseline: 1.0437x; 1.0437x over previous
#include <cuda_runtime.h>
#include <math.h>

// Problem constants
#define B_ 2
#define S_ 2048
#define D_ 1024
#define H_ 16
#define DH_ 64
#define BS_ (B_ * S_)
#define INV_SQRT_DH 0.125f

// Scratch (device globals: no runtime allocation allowed)
__device__ float g_Q[BS_ * D_];        // q projection, [B*S, D] == [B, S, H, DH]
__device__ float g_attn[BS_ * D_];     // per-head attention output (pre out-proj)
__device__ float g_M[H_ * DH_ * DH_];  // folded per-head 64x64 matrices (incl. 1/sqrt(dh))
__device__ float g_kb[B_ * H_ * S_];   // per-key bias: mask ? -||q_t||^2/8 : -9e15

// ---------------------------------------------------------------------------
// C = A @ W^T + bias (+ residual). A:[M,K], W:[N,K] row-major.
// 128x128 tile, BK=16, 256 threads, 8x8 microtile, double-buffered smem.
// ---------------------------------------------------------------------------
template <bool RESID>
__global__ __launch_bounds__(256, 2) void gemm_xwT(
    const float* __restrict__ A, const float* __restrict__ W,
    const float* __restrict__ bias, const float* __restrict__ R,
    float* __restrict__ C, int M, int N, int K)
{
    __shared__ float As[2][16][132];   // [k][m] transposed, pad->2-way store conflicts
    __shared__ float Ws[2][16][132];   // [k][n]
    const int tid = threadIdx.x;
    const int tx = tid & 15, ty = tid >> 4;
    const int m0 = blockIdx.y * 128, n0 = blockIdx.x * 128;
    const int lr = tid >> 2, lk = (tid & 3) * 4;  // loader: row (0..63, +64), k-quad

    float4 ar[2], wr[2];
    // preload tile 0
#pragma unroll
    for (int e = 0; e < 2; e++) {
        ar[e] = *(const float4*)&A[(size_t)(m0 + lr + 64 * e) * K + lk];
        wr[e] = *(const float4*)&W[(size_t)(n0 + lr + 64 * e) * K + lk];
    }
#pragma unroll
    for (int e = 0; e < 2; e++) {
        As[0][lk + 0][lr + 64 * e] = ar[e].x;
        As[0][lk + 1][lr + 64 * e] = ar[e].y;
        As[0][lk + 2][lr + 64 * e] = ar[e].z;
        As[0][lk + 3][lr + 64 * e] = ar[e].w;
        Ws[0][lk + 0][lr + 64 * e] = wr[e].x;
        Ws[0][lk + 1][lr + 64 * e] = wr[e].y;
        Ws[0][lk + 2][lr + 64 * e] = wr[e].z;
        Ws[0][lk + 3][lr + 64 * e] = wr[e].w;
    }
    __syncthreads();

    float acc[8][8] = {};
    const int nk = K / 16;
    for (int t = 0; t < nk; t++) {
        const int cur = t & 1;
        if (t + 1 < nk) {
#pragma unroll
            for (int e = 0; e < 2; e++) {
                ar[e] = *(const float4*)&A[(size_t)(m0 + lr + 64 * e) * K + (t + 1) * 16 + lk];
                wr[e] = *(const float4*)&W[(size_t)(n0 + lr + 64 * e) * K + (t + 1) * 16 + lk];
            }
        }
#pragma unroll
        for (int kk = 0; kk < 16; kk++) {
            float4 a0 = *(const float4*)&As[cur][kk][ty * 8];
            float4 a1 = *(const float4*)&As[cur][kk][ty * 8 + 4];
            float4 b0 = *(const float4*)&Ws[cur][kk][tx * 8];
            float4 b1 = *(const float4*)&Ws[cur][kk][tx * 8 + 4];
            float av[8] = {a0.x, a0.y, a0.z, a0.w, a1.x, a1.y, a1.z, a1.w};
            float bv[8] = {b0.x, b0.y, b0.z, b0.w, b1.x, b1.y, b1.z, b1.w};
#pragma unroll
            for (int i = 0; i < 8; i++)
#pragma unroll
                for (int j = 0; j < 8; j++) acc[i][j] = fmaf(av[i], bv[j], acc[i][j]);
        }
        if (t + 1 < nk) {
            const int nxt = cur ^ 1;
#pragma unroll
            for (int e = 0; e < 2; e++) {
                As[nxt][lk + 0][lr + 64 * e] = ar[e].x;
                As[nxt][lk + 1][lr + 64 * e] = ar[e].y;
                As[nxt][lk + 2][lr + 64 * e] = ar[e].z;
                As[nxt][lk + 3][lr + 64 * e] = ar[e].w;
                Ws[nxt][lk + 0][lr + 64 * e] = wr[e].x;
                Ws[nxt][lk + 1][lr + 64 * e] = wr[e].y;
                Ws[nxt][lk + 2][lr + 64 * e] = wr[e].z;
                Ws[nxt][lk + 3][lr + 64 * e] = wr[e].w;
            }
            __syncthreads();
        }
    }

    float4 bb0 = *(const float4*)&bias[n0 + tx * 8];
    float4 bb1 = *(const float4*)&bias[n0 + tx * 8 + 4];
    float bv[8] = {bb0.x, bb0.y, bb0.z, bb0.w, bb1.x, bb1.y, bb1.z, bb1.w};
#pragma unroll
    for (int i = 0; i < 8; i++) {
        const size_t row = (size_t)(m0 + ty * 8 + i) * N + n0 + tx * 8;
        float o[8];
#pragma unroll
        for (int j = 0; j < 8; j++) o[j] = acc[i][j] + bv[j];
        if (RESID) {
            float4 r0 = *(const float4*)&R[row];
            float4 r1 = *(const float4*)&R[row + 4];
            o[0] += r0.x; o[1] += r0.y; o[2] += r0.z; o[3] += r0.w;
            o[4] += r1.x; o[5] += r1.y; o[6] += r1.z; o[7] += r1.w;
        }
        *(float4*)&C[row]     = make_float4(o[0], o[1], o[2], o[3]);
        *(float4*)&C[row + 4] = make_float4(o[4], o[5], o[6], o[7]);
    }
}

// ---------------------------------------------------------------------------
// M_h[d][f] = sum_e W_q[e, h*DH+d] * W_v[e, h*DH+f], scaled by 1/sqrt(dh).
// ---------------------------------------------------------------------------
__global__ __launch_bounds__(256) void compute_M_kernel(
    const float* __restrict__ Wq, const float* __restrict__ Wv)
{
    __shared__ float Aq[32][68];
    __shared__ float Av[32][68];
    const int h = blockIdx.x;
    const int tid = threadIdx.x;
    const int tx = tid & 15, ty = tid >> 4;

    float acc[4][4] = {};
    for (int e0 = 0; e0 < D_; e0 += 32) {
#pragma unroll
        for (int e = 0; e < 8; e++) {
            int idx = tid + e * 256;
            int ee = idx >> 6, c = idx & 63;
            Aq[ee][c] = Wq[(size_t)(e0 + ee) * D_ + h * DH_ + c];
            Av[ee][c] = Wv[(size_t)(e0 + ee) * D_ + h * DH_ + c];
        }
        __syncthreads();
#pragma unroll
        for (int ee = 0; ee < 32; ee++) {
            float4 a4 = *(const float4*)&Aq[ee][ty * 4];
            float4 b4 = *(const float4*)&Av[ee][tx * 4];
            float av[4] = {a4.x, a4.y, a4.z, a4.w};
            float bv[4] = {b4.x, b4.y, b4.z, b4.w};
#pragma unroll
            for (int i = 0; i < 4; i++)
#pragma unroll
                for (int j = 0; j < 4; j++) acc[i][j] += av[i] * bv[j];
        }
        __syncthreads();
    }
#pragma unroll
    for (int i = 0; i < 4; i++)
#pragma unroll
        for (int j = 0; j < 4; j++)
            g_M[h * DH_ * DH_ + (ty * 4 + i) * DH_ + tx * 4 + j] =
                acc[i][j] * INV_SQRT_DH;
}

// ---------------------------------------------------------------------------
// Per-key bias: g_kb[b,h,t] = mask ? -||q_{b,h,t}||^2 / sqrt(dh) : -9e15
// ---------------------------------------------------------------------------
__global__ __launch_bounds__(256) void compute_kb_kernel(const int* __restrict__ mask)
{
    const int idx = blockIdx.x * 256 + threadIdx.x;  // 0 .. B*H*S-1
    const int t = idx & (S_ - 1);
    const int bh = idx >> 11;
    const int b = bh >> 4, h = bh & 15;
    const float* q = g_Q + (size_t)(b * S_ + t) * D_ + h * DH_;
    float s = 0.0f;
#pragma unroll
    for (int d = 0; d < DH_; d += 4) {
        float4 v = *(const float4*)&q[d];
        s += v.x * v.x + v.y * v.y + v.z * v.z + v.w * v.w;
    }
    g_kb[bh * S_ + t] = (mask[b * S_ + t] == 0) ? -9e15f : (-s * INV_SQRT_DH);
}

// ---------------------------------------------------------------------------
// Flash-style L2 attention. Block = (b,h) x 128-query tile; Bc=64 keys/iter.
// score = 0.25 * (q_r . q_t) + kb[t]  (row-constant term cancels in softmax).
// 256 threads, 8x4 microtile; thread cols t = tx + 16j.
// Smem: Qs [d][r] (f4+broadcast reads), Kdt [d][t] (QK), Ktd [t][d] (PV, V=K),
//       Ps [t][r] (P^T, f4 reads in PV). All reads float4 or broadcast.
// ---------------------------------------------------------------------------
__global__ __launch_bounds__(256, 2) void attn_kernel()
{
    extern __shared__ float sm[];
    float* Qs  = sm;                  // [64][132]  (d, r)
    float* Kdt = sm + 64 * 132;       // [64][68]   (d, t)  -- also M[f][g] in epilogue
    float* Ktd = Kdt + 64 * 68;       // [64][68]   (t, d)
    float* Ps  = Ktd + 64 * 68;       // [64][132]  (t, r)  -- also O^T[f][r] in epilogue

    const int tid = threadIdx.x;
    const int tx = tid & 15, ty = tid >> 4;
    const int qt = blockIdx.x;         // 16 query tiles of 128
    const int bh = blockIdx.y;         // 32 (b,h)
    const int b = bh >> 4, h = bh & 15;
    const float* Qg = g_Q + (size_t)b * S_ * D_ + h * DH_;
    const float* kbp = g_kb + bh * S_;

    // Load Q tile (128 x 64) transposed into Qs[d][r]
    {
        const int r = tid >> 1, half = tid & 1;
        const float* src = Qg + (size_t)(qt * 128 + r) * D_ + half * 32;
#pragma unroll
        for (int e = 0; e < 8; e++) {
            float4 v = *(const float4*)(src + e * 4);
            const int d = half * 32 + e * 4;
            Qs[(d + 0) * 132 + r] = v.x;
            Qs[(d + 1) * 132 + r] = v.y;
            Qs[(d + 2) * 132 + r] = v.z;
            Qs[(d + 3) * 132 + r] = v.w;
        }
    }

    // K-tile loader: row t = tid>>2, d-quad group = (tid&3)*16
    const int kr = tid >> 2, kq = (tid & 3) * 16;
    float4 kreg[4];
#pragma unroll
    for (int e = 0; e < 4; e++)
        kreg[e] = *(const float4*)(Qg + (size_t)kr * D_ + kq + e * 4);

    float Oacc[8][4] = {};
    float mrow[8], lrow[8];
#pragma unroll
    for (int i = 0; i < 8; i++) { mrow[i] = -1e30f; lrow[i] = 0.0f; }

    for (int kt = 0; kt < S_ / 64; kt++) {
        __syncthreads();  // prev PV done reading Ps/Ktd; Q visible on iter 0
        // Commit staged K tile: Ktd[t][d] (f4) + Kdt[d][t] (scatter, 2-way)
#pragma unroll
        for (int e = 0; e < 4; e++) {
            const int d = kq + e * 4;
            float4 v = kreg[e];
            *(float4*)&Ktd[kr * 68 + d] = v;
            Kdt[(d + 0) * 68 + kr] = v.x;
            Kdt[(d + 1) * 68 + kr] = v.y;
            Kdt[(d + 2) * 68 + kr] = v.z;
            Kdt[(d + 3) * 68 + kr] = v.w;
        }
        __syncthreads();
        // Prefetch next K tile into registers (overlaps QK+PV compute)
        if (kt + 1 < S_ / 64) {
            const float* src = Qg + (size_t)((kt + 1) * 64 + kr) * D_ + kq;
#pragma unroll
            for (int e = 0; e < 4; e++) kreg[e] = *(const float4*)(src + e * 4);
        }

        // ---- S = Q @ K^T  (8 rows x 4 key-cols, cols t = tx + 16j) ----
        float sc[8][4] = {};
#pragma unroll
        for (int d = 0; d < 64; d++) {
            float4 a0 = *(const float4*)&Qs[d * 132 + ty * 8];
            float4 a1 = *(const float4*)&Qs[d * 132 + ty * 8 + 4];
            float av[8] = {a0.x, a0.y, a0.z, a0.w, a1.x, a1.y, a1.z, a1.w};
            float bv[4];
#pragma unroll
            for (int j = 0; j < 4; j++) bv[j] = Kdt[d * 68 + tx + 16 * j];
#pragma unroll
            for (int i = 0; i < 8; i++)
#pragma unroll
                for (int j = 0; j < 4; j++) sc[i][j] = fmaf(av[i], bv[j], sc[i][j]);
        }
        float kbv[4];
#pragma unroll
        for (int j = 0; j < 4; j++) kbv[j] = kbp[kt * 64 + tx + 16 * j];
#pragma unroll
        for (int i = 0; i < 8; i++)
#pragma unroll
            for (int j = 0; j < 4; j++)
                sc[i][j] = sc[i][j] * (2.0f * INV_SQRT_DH) + kbv[j];

        // ---- online softmax (row spread over 16 lanes) ----
#pragma unroll
        for (int i = 0; i < 8; i++) {
            float mloc = fmaxf(fmaxf(sc[i][0], sc[i][1]), fmaxf(sc[i][2], sc[i][3]));
#pragma unroll
            for (int off = 8; off > 0; off >>= 1)
                mloc = fmaxf(mloc, __shfl_xor_sync(0xffffffffu, mloc, off, 16));
            const float mnew = fmaxf(mrow[i], mloc);
            const float alpha = __expf(mrow[i] - mnew);
            float psum = 0.0f;
#pragma unroll
            for (int j = 0; j < 4; j++) {
                const float p = __expf(sc[i][j] - mnew);
                sc[i][j] = p;
                psum += p;
            }
#pragma unroll
            for (int off = 8; off > 0; off >>= 1)
                psum += __shfl_xor_sync(0xffffffffu, psum, off, 16);
            lrow[i] = lrow[i] * alpha + psum;
            mrow[i] = mnew;
#pragma unroll
            for (int j = 0; j < 4; j++) Oacc[i][j] *= alpha;
#pragma unroll
            for (int j = 0; j < 4; j++)
                Ps[(tx + 16 * j) * 132 + ty * 8 + i] = sc[i][j];
        }
        __syncthreads();

        // ---- O += P @ K (values ARE the keys) ----
#pragma unroll
        for (int t = 0; t < 64; t++) {
            float4 p0 = *(const float4*)&Ps[t * 132 + ty * 8];
            float4 p1 = *(const float4*)&Ps[t * 132 + ty * 8 + 4];
            float4 kv = *(const float4*)&Ktd[t * 68 + tx * 4];
            float av[8] = {p0.x, p0.y, p0.z, p0.w, p1.x, p1.y, p1.z, p1.w};
            float bv[4] = {kv.x, kv.y, kv.z, kv.w};
#pragma unroll
            for (int i = 0; i < 8; i++)
#pragma unroll
                for (int j = 0; j < 4; j++) Oacc[i][j] = fmaf(av[i], bv[j], Oacc[i][j]);
        }
    }

    // ---- Epilogue: O2 = (O / l) @ M_h ----
    __syncthreads();
    // Store normalized O transposed into Ps as [f][r]
#pragma unroll
    for (int i = 0; i < 8; i++) {
        const float inv = 1.0f / lrow[i];
#pragma unroll
        for (int j = 0; j < 4; j++)
            Ps[(tx * 4 + j) * 132 + ty * 8 + i] = Oacc[i][j] * inv;
    }
    // Load M_h into Kdt region as [f][g], row pad 68
    {
        const int f = tid >> 2;
        const float* src = g_M + h * DH_ * DH_ + f * 64 + (tid & 3) * 16;
#pragma unroll
        for (int e = 0; e < 4; e++)
            *(float4*)&Kdt[f * 68 + (tid & 3) * 16 + e * 4] = *(const float4*)(src + e * 4);
    }
    __syncthreads();

    float o2[8][4] = {};
#pragma unroll
    for (int f = 0; f < 64; f++) {
        float4 a0 = *(const float4*)&Ps[f * 132 + ty * 8];
        float4 a1 = *(const float4*)&Ps[f * 132 + ty * 8 + 4];
        float4 mv = *(const float4*)&Kdt[f * 68 + tx * 4];
        float av[8] = {a0.x, a0.y, a0.z, a0.w, a1.x, a1.y, a1.z, a1.w};
        float bv[4] = {mv.x, mv.y, mv.z, mv.w};
#pragma unroll
        for (int i = 0; i < 8; i++)
#pragma unroll
            for (int j = 0; j < 4; j++) o2[i][j] = fmaf(av[i], bv[j], o2[i][j]);
    }
    float* Og = g_attn + (size_t)b * S_ * D_ + h * DH_;
#pragma unroll
    for (int i = 0; i < 8; i++)
        *(float4*)&Og[(size_t)(qt * 128 + ty * 8 + i) * D_ + tx * 4] =
            make_float4(o2[i][0], o2[i][1], o2[i][2], o2[i][3]);
}

// ---------------------------------------------------------------------------
// Launch
// ---------------------------------------------------------------------------
extern "C" void kernel_launch(void* const* d_in, const int* in_sizes, int n_in,
                              void* d_out, int out_size)
{
    // metadata order: x, W_q, b_q, W_v, W_out, b_out, mask
    const float* x     = (const float*)d_in[0];
    const float* W_q   = (const float*)d_in[1];
    const float* b_q   = (const float*)d_in[2];
    const float* W_v   = (const float*)d_in[3];
    const float* W_out = (const float*)d_in[4];
    const float* b_out = (const float*)d_in[5];
    const int*   mask  = (const int*)d_in[6];
    float* out = (float*)d_out;

    float *pQ, *pA;
    cudaGetSymbolAddress((void**)&pQ, g_Q);
    cudaGetSymbolAddress((void**)&pA, g_attn);

    dim3 gge(D_ / 128, BS_ / 128);

    // 1) Q = x @ W_q^T + b_q
    gemm_xwT<false><<<gge, 256>>>(x, W_q, b_q, nullptr, pQ, BS_, D_, D_);

    // 2) per-head folded matrices M_h
    compute_M_kernel<<<H_, 256>>>(W_q, W_v);

    // 3) per-key masked bias
    compute_kb_kernel<<<(B_ * H_ * S_) / 256, 256>>>(mask);

    // 4) attention (flash-style, 128-query tiles) + per-head epilogue
    const int smemB = (2 * 64 * 132 + 2 * 64 * 68) * (int)sizeof(float);  // 102400 B
    cudaFuncSetAttribute(attn_kernel, cudaFuncAttributeMaxDynamicSharedMemorySize, smemB);
    attn_kernel<<<dim3(S_ / 128, B_ * H_), 256, smemB>>>();

    // 5) out = x + attn @ W_out^T + b_out
    gemm_xwT<true><<<gge, 256>>>(pA, W_out, b_out, x, out, BS_, D_, D_);
}

// round 14
// speedup vs baseline: 2.1820x; 2.0907x over previous
#include <cuda_runtime.h>
#include <cuda_bf16.h>
#include <cstdint>
#include <math.h>

// Problem constants
#define B_ 2
#define S_ 2048
#define D_ 1024
#define H_ 16
#define DH_ 64
#define BS_ (B_ * S_)
#define INV_SQRT_DH 0.125f
#define NKT64 (S_ / 64)         // 32 key tiles of 64
#define C1 0.3606738f           // 0.25 * log2(e)  (score scale folded into exp2)
#define LOG2E 1.4426950f

// Scratch (device globals: no runtime allocation allowed)
__device__ float g_Q[BS_ * D_];            // q projection fp32, [B,S,H,DH]
__device__ __nv_bfloat16 g_Qbf[BS_ * D_];  // q bf16, head-major [B,H,S,DH]
__device__ float g_attn[BS_ * D_];         // O/l, [B,S,H,DH]
__device__ float g_M[H_ * DH_ * DH_];      // per-head 64x64 (incl. 1/sqrt(dh))
__device__ float g_Wt[D_ * D_];            // folded W_out @ M  ([n][h*64+d])
__device__ float g_kb2[B_ * H_ * S_];      // log2e * (mask ? -||q_t||^2/8 : -9e15)

// ===========================================================================
// Warp-level bf16 MMA (sm_80+ PTX; HMMA fallback pipe on sm_103)
// D(16x8,f32) += A(16x16,bf16,row) * B(16x8,bf16,col)
// ===========================================================================
__device__ __forceinline__ void mma16816(float c[4], const uint32_t a[4],
                                         uint32_t b0, uint32_t b1) {
    asm volatile(
        "mma.sync.aligned.m16n8k16.row.col.f32.bf16.bf16.f32 "
        "{%0,%1,%2,%3}, {%4,%5,%6,%7}, {%8,%9}, {%0,%1,%2,%3};"
        : "+f"(c[0]), "+f"(c[1]), "+f"(c[2]), "+f"(c[3])
        : "r"(a[0]), "r"(a[1]), "r"(a[2]), "r"(a[3]), "r"(b0), "r"(b1));
}
__device__ __forceinline__ float ex2f(float x) {
    float r;
    asm("ex2.approx.f32 %0, %1;" : "=f"(r) : "f"(x));
    return r;
}
__device__ __forceinline__ uint32_t packbf2(float x, float y) {
    __nv_bfloat162 p = __floats2bfloat162_rn(x, y);
    return *(uint32_t*)&p;
}

// ===========================================================================
// Dense GEMM: C = A @ W^T + bias (+R).  128x128 tile, BK=16, 8x8 microtile.
// ===========================================================================
template <bool RESID>
__global__ __launch_bounds__(256, 2) void gemm_xwT(
    const float* __restrict__ A, const float* __restrict__ W,
    const float* __restrict__ bias, const float* __restrict__ R,
    float* __restrict__ C, int M, int N, int K)
{
    __shared__ float As[2][16][132];
    __shared__ float Ws[2][16][132];
    const int tid = threadIdx.x;
    const int tx = tid & 15, ty = tid >> 4;
    const int m0 = blockIdx.y * 128, n0 = blockIdx.x * 128;
    const int lr = tid >> 2, lk = (tid & 3) * 4;

    float4 ar[2], wr[2];
#pragma unroll
    for (int e = 0; e < 2; e++) {
        ar[e] = *(const float4*)&A[(size_t)(m0 + lr + 64 * e) * K + lk];
        wr[e] = *(const float4*)&W[(size_t)(n0 + lr + 64 * e) * K + lk];
    }
#pragma unroll
    for (int e = 0; e < 2; e++) {
        As[0][lk + 0][lr + 64 * e] = ar[e].x; As[0][lk + 1][lr + 64 * e] = ar[e].y;
        As[0][lk + 2][lr + 64 * e] = ar[e].z; As[0][lk + 3][lr + 64 * e] = ar[e].w;
        Ws[0][lk + 0][lr + 64 * e] = wr[e].x; Ws[0][lk + 1][lr + 64 * e] = wr[e].y;
        Ws[0][lk + 2][lr + 64 * e] = wr[e].z; Ws[0][lk + 3][lr + 64 * e] = wr[e].w;
    }
    __syncthreads();

    float acc[8][8] = {};
    const int nk = K / 16;
    for (int t = 0; t < nk; t++) {
        const int cur = t & 1;
        if (t + 1 < nk) {
#pragma unroll
            for (int e = 0; e < 2; e++) {
                ar[e] = *(const float4*)&A[(size_t)(m0 + lr + 64 * e) * K + (t + 1) * 16 + lk];
                wr[e] = *(const float4*)&W[(size_t)(n0 + lr + 64 * e) * K + (t + 1) * 16 + lk];
            }
        }
#pragma unroll
        for (int kk = 0; kk < 16; kk++) {
            float4 a0 = *(const float4*)&As[cur][kk][ty * 8];
            float4 a1 = *(const float4*)&As[cur][kk][ty * 8 + 4];
            float4 b0 = *(const float4*)&Ws[cur][kk][tx * 8];
            float4 b1 = *(const float4*)&Ws[cur][kk][tx * 8 + 4];
            float av[8] = {a0.x, a0.y, a0.z, a0.w, a1.x, a1.y, a1.z, a1.w};
            float bv[8] = {b0.x, b0.y, b0.z, b0.w, b1.x, b1.y, b1.z, b1.w};
#pragma unroll
            for (int i = 0; i < 8; i++)
#pragma unroll
                for (int j = 0; j < 8; j++) acc[i][j] = fmaf(av[i], bv[j], acc[i][j]);
        }
        if (t + 1 < nk) {
            const int nxt = cur ^ 1;
#pragma unroll
            for (int e = 0; e < 2; e++) {
                As[nxt][lk + 0][lr + 64 * e] = ar[e].x; As[nxt][lk + 1][lr + 64 * e] = ar[e].y;
                As[nxt][lk + 2][lr + 64 * e] = ar[e].z; As[nxt][lk + 3][lr + 64 * e] = ar[e].w;
                Ws[nxt][lk + 0][lr + 64 * e] = wr[e].x; Ws[nxt][lk + 1][lr + 64 * e] = wr[e].y;
                Ws[nxt][lk + 2][lr + 64 * e] = wr[e].z; Ws[nxt][lk + 3][lr + 64 * e] = wr[e].w;
            }
            __syncthreads();
        }
    }

    float4 bb0 = *(const float4*)&bias[n0 + tx * 8];
    float4 bb1 = *(const float4*)&bias[n0 + tx * 8 + 4];
    float bv[8] = {bb0.x, bb0.y, bb0.z, bb0.w, bb1.x, bb1.y, bb1.z, bb1.w};
#pragma unroll
    for (int i = 0; i < 8; i++) {
        const size_t row = (size_t)(m0 + ty * 8 + i) * N + n0 + tx * 8;
        float o[8];
#pragma unroll
        for (int j = 0; j < 8; j++) o[j] = acc[i][j] + bv[j];
        if (RESID) {
            float4 r0 = *(const float4*)&R[row];
            float4 r1 = *(const float4*)&R[row + 4];
            o[0] += r0.x; o[1] += r0.y; o[2] += r0.z; o[3] += r0.w;
            o[4] += r1.x; o[5] += r1.y; o[6] += r1.z; o[7] += r1.w;
        }
        *(float4*)&C[row]     = make_float4(o[0], o[1], o[2], o[3]);
        *(float4*)&C[row + 4] = make_float4(o[4], o[5], o[6], o[7]);
    }
}

// ===========================================================================
// M_h[d][f] = sum_e W_q[e, h*64+d] * W_v[e, h*64+f] * 0.125
// ===========================================================================
__global__ __launch_bounds__(256) void compute_M_kernel(
    const float* __restrict__ Wq, const float* __restrict__ Wv)
{
    __shared__ float Aq[32][68];
    __shared__ float Av[32][68];
    const int h = blockIdx.x;
    const int tid = threadIdx.x;
    const int tx = tid & 15, ty = tid >> 4;

    float acc[4][4] = {};
    for (int e0 = 0; e0 < D_; e0 += 32) {
#pragma unroll
        for (int e = 0; e < 8; e++) {
            int idx = tid + e * 256;
            int ee = idx >> 6, c = idx & 63;
            Aq[ee][c] = Wq[(size_t)(e0 + ee) * D_ + h * DH_ + c];
            Av[ee][c] = Wv[(size_t)(e0 + ee) * D_ + h * DH_ + c];
        }
        __syncthreads();
#pragma unroll
        for (int ee = 0; ee < 32; ee++) {
            float4 a4 = *(const float4*)&Aq[ee][ty * 4];
            float4 b4 = *(const float4*)&Av[ee][tx * 4];
            float av[4] = {a4.x, a4.y, a4.z, a4.w};
            float bv[4] = {b4.x, b4.y, b4.z, b4.w};
#pragma unroll
            for (int i = 0; i < 4; i++)
#pragma unroll
                for (int j = 0; j < 4; j++) acc[i][j] += av[i] * bv[j];
        }
        __syncthreads();
    }
#pragma unroll
    for (int i = 0; i < 4; i++)
#pragma unroll
        for (int j = 0; j < 4; j++)
            g_M[h * DH_ * DH_ + (ty * 4 + i) * DH_ + tx * 4 + j] = acc[i][j] * INV_SQRT_DH;
}

// ===========================================================================
// Fold: Wt[n, h*64+d] = sum_f W_out[n, h*64+f] * M_h[d][f]
// ===========================================================================
__global__ __launch_bounds__(256) void fold_wout_kernel(const float* __restrict__ Wout)
{
    __shared__ float Msm[64][68];   // [f][d]
    const int h = blockIdx.x & 15;
    const int n0 = (blockIdx.x >> 4) * 64;
    const int tid = threadIdx.x;

#pragma unroll
    for (int e = 0; e < 16; e++) {
        int i = tid + e * 256;
        int f = i & 63, d = i >> 6;
        Msm[f][d] = g_M[h * 4096 + d * 64 + f];
    }
    __syncthreads();

    const int n = n0 + (tid >> 2), dg = (tid & 3) * 16;
    float acc[16] = {};
    const float* wrow = Wout + (size_t)n * D_ + h * 64;
    for (int f = 0; f < 64; f++) {
        float wv = wrow[f];
#pragma unroll
        for (int q = 0; q < 4; q++) {
            float4 m4 = *(const float4*)&Msm[f][dg + q * 4];
            acc[q * 4 + 0] = fmaf(wv, m4.x, acc[q * 4 + 0]);
            acc[q * 4 + 1] = fmaf(wv, m4.y, acc[q * 4 + 1]);
            acc[q * 4 + 2] = fmaf(wv, m4.z, acc[q * 4 + 2]);
            acc[q * 4 + 3] = fmaf(wv, m4.w, acc[q * 4 + 3]);
        }
    }
    float* dst = g_Wt + (size_t)n * D_ + h * 64 + dg;
#pragma unroll
    for (int q = 0; q < 4; q++)
        *(float4*)&dst[q * 4] = make_float4(acc[q*4], acc[q*4+1], acc[q*4+2], acc[q*4+3]);
}

// ===========================================================================
// Convert: g_Q [B,S,H,DH] fp32 -> g_Qbf [B,H,S,DH] bf16; kb2 = log2e * bias
// ===========================================================================
__global__ __launch_bounds__(256) void convert_q_kernel(const int* __restrict__ mask)
{
    const int idx = blockIdx.x * 256 + threadIdx.x;   // 0..65535
    const int s = idx & (S_ - 1);
    const int bh = idx >> 11;
    const int b = bh >> 4, h = bh & 15;
    const float* src = g_Q + (size_t)(b * S_ + s) * D_ + h * DH_;
    float sq = 0.0f;
    uint32_t u[32];
#pragma unroll
    for (int j = 0; j < 64; j += 4) {
        float4 v = *(const float4*)&src[j];
        sq += v.x * v.x + v.y * v.y + v.z * v.z + v.w * v.w;
        u[j / 2]     = packbf2(v.x, v.y);
        u[j / 2 + 1] = packbf2(v.z, v.w);
    }
    uint4* dst = (uint4*)(g_Qbf + (size_t)(bh * S_ + s) * DH_);
#pragma unroll
    for (int e = 0; e < 8; e++)
        dst[e] = make_uint4(u[e*4], u[e*4+1], u[e*4+2], u[e*4+3]);
    const float kb = -sq * INV_SQRT_DH;
    g_kb2[bh * S_ + s] = (mask[b * S_ + s] == 0) ? -1.3e16f : kb * LOG2E;
}

// ===========================================================================
// Flash attention on warp-level bf16 HMMA.  Block = (b,h) x 128-query tile.
// 8 warps x 16 query rows; Bc=64 keys/iter.  p = exp2(C1*S + kb2), no row max.
// K tile kept in both [t][d] (QK B-frags) and [d][t] (PV B-frags; V = K).
// P never leaves registers (S C-frag layout == PV A-frag layout).
// ===========================================================================
__global__ __launch_bounds__(256, 2) void attn_kernel()
{
    __shared__ __align__(16) __nv_bfloat16 sKtd[2][64][72];  // [t][d], stride 144B
    __shared__ __align__(16) __nv_bfloat16 sKdt[2][64][72];  // [d][t]
    __shared__ float kb_sm[2][64];

    const int tid = threadIdx.x;
    const int wid = tid >> 5, lane = tid & 31;
    const int lg = lane >> 2;        // fragment row group 0..7
    const int qc = (lane & 3) * 2;   // fragment col pair base
    const int qt = blockIdx.x;
    const int bh = blockIdx.y;
    const int b = bh >> 4, h = bh & 15;
    const __nv_bfloat16* Qbf = g_Qbf + (size_t)bh * S_ * DH_;
    const float* kb2 = g_kb2 + bh * S_;

    // Q A-fragments (held in registers for all iterations)
    const int r0 = qt * 128 + wid * 16 + lg;
    uint32_t qa[4][4];
#pragma unroll
    for (int k = 0; k < 4; k++) {
        qa[k][0] = *(const uint32_t*)&Qbf[(size_t)r0 * DH_ + k * 16 + qc];
        qa[k][1] = *(const uint32_t*)&Qbf[(size_t)(r0 + 8) * DH_ + k * 16 + qc];
        qa[k][2] = *(const uint32_t*)&Qbf[(size_t)r0 * DH_ + k * 16 + qc + 8];
        qa[k][3] = *(const uint32_t*)&Qbf[(size_t)(r0 + 8) * DH_ + k * 16 + qc + 8];
    }

    // K loader mapping: row t = tid>>2, d block = (tid&3)*16 (32B per thread)
    const int lt = tid >> 2, ldd = (tid & 3) * 16;

    // Prologue: stage K(0), kb(0) into buffer 0
    {
        const __nv_bfloat16* src = Qbf + (size_t)lt * DH_ + ldd;
        uint4 v0 = *(const uint4*)src;
        uint4 v1 = *(const uint4*)(src + 8);
        *(uint4*)&sKtd[0][lt][ldd]     = v0;
        *(uint4*)&sKtd[0][lt][ldd + 8] = v1;
        const __nv_bfloat16* e0 = (const __nv_bfloat16*)&v0;
        const __nv_bfloat16* e1 = (const __nv_bfloat16*)&v1;
#pragma unroll
        for (int i = 0; i < 8; i++) {
            sKdt[0][ldd + i][lt]     = e0[i];
            sKdt[0][ldd + 8 + i][lt] = e1[i];
        }
        if (tid < 64) kb_sm[0][tid] = kb2[tid];
    }
    __syncthreads();

    float lacc0 = 0.0f, lacc1 = 0.0f;
    float oacc[8][4] = {};

    for (int kt = 0; kt < NKT64; kt++) {
        const int buf = kt & 1;
        const bool pf = (kt + 1 < NKT64);
        uint4 v0, v1;
        float kbv = 0.0f;
        if (pf) {
            const __nv_bfloat16* src = Qbf + (size_t)((kt + 1) * 64 + lt) * DH_ + ldd;
            v0 = *(const uint4*)src;
            v1 = *(const uint4*)(src + 8);
            if (tid < 64) kbv = kb2[(kt + 1) * 64 + tid];
        }

        // ---- S = Q @ K^T : 8 n-tiles (8 keys each) x 4 k-steps ----
        float sc[8][4];
#pragma unroll
        for (int nt = 0; nt < 8; nt++) {
            sc[nt][0] = sc[nt][1] = sc[nt][2] = sc[nt][3] = 0.0f;
#pragma unroll
            for (int k = 0; k < 4; k++) {
                uint32_t b0 = *(const uint32_t*)&sKtd[buf][nt * 8 + lg][k * 16 + qc];
                uint32_t b1 = *(const uint32_t*)&sKtd[buf][nt * 8 + lg][k * 16 + qc + 8];
                mma16816(sc[nt], qa[k], b0, b1);
            }
        }

        // ---- softmax: p = exp2(C1*s + kb2[t]); accumulate l; pack bf16 ----
        uint32_t pk[8][2];
#pragma unroll
        for (int nt = 0; nt < 8; nt++) {
            float2 kbp = *(const float2*)&kb_sm[buf][nt * 8 + qc];
            float p0 = ex2f(fmaf(sc[nt][0], C1, kbp.x));
            float p1 = ex2f(fmaf(sc[nt][1], C1, kbp.y));
            float p2 = ex2f(fmaf(sc[nt][2], C1, kbp.x));
            float p3 = ex2f(fmaf(sc[nt][3], C1, kbp.y));
            lacc0 += p0 + p1;
            lacc1 += p2 + p3;
            pk[nt][0] = packbf2(p0, p1);
            pk[nt][1] = packbf2(p2, p3);
        }

        // ---- O += P @ K : A-frags from pk (C layout == A layout trick) ----
#pragma unroll
        for (int tk = 0; tk < 4; tk++) {
            uint32_t pa[4] = {pk[2 * tk][0], pk[2 * tk][1],
                              pk[2 * tk + 1][0], pk[2 * tk + 1][1]};
#pragma unroll
            for (int nt = 0; nt < 8; nt++) {
                uint32_t b0 = *(const uint32_t*)&sKdt[buf][nt * 8 + lg][tk * 16 + qc];
                uint32_t b1 = *(const uint32_t*)&sKdt[buf][nt * 8 + lg][tk * 16 + qc + 8];
                mma16816(oacc[nt], pa, b0, b1);
            }
        }

        // ---- commit prefetched K(kt+1) into the other buffer ----
        if (pf) {
            const int nb = buf ^ 1;
            *(uint4*)&sKtd[nb][lt][ldd]     = v0;
            *(uint4*)&sKtd[nb][lt][ldd + 8] = v1;
            const __nv_bfloat16* e0 = (const __nv_bfloat16*)&v0;
            const __nv_bfloat16* e1 = (const __nv_bfloat16*)&v1;
#pragma unroll
            for (int i = 0; i < 8; i++) {
                sKdt[nb][ldd + i][lt]     = e0[i];
                sKdt[nb][ldd + 8 + i][lt] = e1[i];
            }
            if (tid < 64) kb_sm[nb][tid] = kbv;
        }
        __syncthreads();
    }

    // ---- epilogue: O / l -> g_attn ----
    lacc0 += __shfl_xor_sync(0xffffffffu, lacc0, 1);
    lacc0 += __shfl_xor_sync(0xffffffffu, lacc0, 2);
    lacc1 += __shfl_xor_sync(0xffffffffu, lacc1, 1);
    lacc1 += __shfl_xor_sync(0xffffffffu, lacc1, 2);
    const float inv0 = 1.0f / lacc0;
    const float inv1 = 1.0f / lacc1;

    const size_t grow0 = (size_t)(b * S_ + qt * 128 + wid * 16 + lg) * D_ + h * DH_;
    const size_t grow1 = grow0 + 8 * D_;
#pragma unroll
    for (int nt = 0; nt < 8; nt++) {
        const int d = nt * 8 + qc;
        *(float2*)&g_attn[grow0 + d] = make_float2(oacc[nt][0] * inv0, oacc[nt][1] * inv0);
        *(float2*)&g_attn[grow1 + d] = make_float2(oacc[nt][2] * inv1, oacc[nt][3] * inv1);
    }
}

// ===========================================================================
// Launch
// ===========================================================================
extern "C" void kernel_launch(void* const* d_in, const int* in_sizes, int n_in,
                              void* d_out, int out_size)
{
    // metadata order: x, W_q, b_q, W_v, W_out, b_out, mask
    const float* x     = (const float*)d_in[0];
    const float* W_q   = (const float*)d_in[1];
    const float* b_q   = (const float*)d_in[2];
    const float* W_v   = (const float*)d_in[3];
    const float* W_out = (const float*)d_in[4];
    const float* b_out = (const float*)d_in[5];
    const int*   mask  = (const int*)d_in[6];
    float* out = (float*)d_out;

    float *pQ, *pA, *pWt;
    cudaGetSymbolAddress((void**)&pQ,  g_Q);
    cudaGetSymbolAddress((void**)&pA,  g_attn);
    cudaGetSymbolAddress((void**)&pWt, g_Wt);

    dim3 gge(D_ / 128, BS_ / 128);

    // 1) Q = x @ W_q^T + b_q (fp32)
    gemm_xwT<false><<<gge, 256>>>(x, W_q, b_q, nullptr, pQ, BS_, D_, D_);

    // 2) bf16 head-major Q + per-key bias
    convert_q_kernel<<<(BS_ * H_) / 256, 256>>>(mask);

    // 3) per-head M, folded into W_out
    compute_M_kernel<<<H_, 256>>>(W_q, W_v);
    fold_wout_kernel<<<H_ * (D_ / 64), 256>>>(W_out);

    // 4) attention (warp-level bf16 HMMA flash)
    attn_kernel<<<dim3(S_ / 128, B_ * H_), 256>>>();

    // 5) out = x + (O/l) @ Wt^T + b_out
    gemm_xwT<true><<<gge, 256>>>(pA, pWt, b_out, x, out, BS_, D_, D_);
}